// round 6
// baseline (speedup 1.0000x reference)
#include <cuda_runtime.h>
#include <cuda_bf16.h>
#include <cstdint>

// Problem constants (shapes are fixed by the dataset)
#define D      256
#define KSUB   3686
#define KPAD   3712          // 29 * 128
#define NCHUNK 29
#define BK     128           // codes per chunk
#define BM     128           // tokens per block
#define NTOK   16384         // 32*512
#define NTOKEL 4194304       // NTOK * D
#define NSLICE (NCHUNK * 8)  // 232 ds-slices total

// ---------------- device scratch (no allocations allowed) ----------------
__device__ float g_sub[KPAD * D];    // packed (dropout-subsampled) codebook, padded
__device__ float g_c2[KPAD];         // per-code squared norms (pad rows = +huge)
__device__ int   g_gidx[KPAD];       // global codebook index per packed row
__device__ float g_loss;             // loss accumulator

// packed f32x2 FMA: d += a * b (elementwise on the pair) — Blackwell FFMA2
__device__ __forceinline__ void ffma2(float2& d, const float2& a, const float2& b) {
    unsigned long long&       dd = reinterpret_cast<unsigned long long&>(d);
    const unsigned long long& aa = reinterpret_cast<const unsigned long long&>(a);
    const unsigned long long& bb = reinterpret_cast<const unsigned long long&>(b);
    asm("fma.rn.f32x2 %0, %1, %2, %0;" : "+l"(dd) : "l"(aa), "l"(bb));
}

// ---------------- Kernel A: gather sub-codebook + c2, zero loss ----------------
__global__ void pack_kernel(const float* __restrict__ codebook,
                            const int*   __restrict__ rind) {
    int r   = blockIdx.x;          // packed row 0..KPAD-1
    int tid = threadIdx.x;         // 64 threads, one float4 each (256 floats/row)
    if (r == 0 && tid == 0) g_loss = 0.0f;

    __shared__ float sh[2];
    float4 v;
    int gi = 0;
    if (r < KSUB) {
        gi = rind[r];
        v = reinterpret_cast<const float4*>(codebook + (size_t)gi * D)[tid];
    } else {
        v = make_float4(0.f, 0.f, 0.f, 0.f);
    }
    reinterpret_cast<float4*>(g_sub + (size_t)r * D)[tid] = v;

    float s = v.x * v.x + v.y * v.y + v.z * v.z + v.w * v.w;
    #pragma unroll
    for (int off = 16; off > 0; off >>= 1)
        s += __shfl_down_sync(0xffffffffu, s, off);
    if ((tid & 31) == 0) sh[tid >> 5] = s;
    __syncthreads();
    if (tid == 0) {
        g_c2[r]   = (r < KSUB) ? (sh[0] + sh[1]) : 1.0e30f;
        g_gidx[r] = gi;
    }
}

// ---------------- Kernel B: fused GEMM-argmin + gather + loss ----------------
// smem layout (floats):
//   xs  [256][130]  : transposed x tile (token-major inner), 33280 floats
//   cs  [32][128]   : transposed code-dim slice, 4096 floats (reused as argmin scratch)
//   c2s [128]       : per-chunk c2 (reused as bestk[128] ints)
#define XS_STRIDE 130
#define SMEM_B_BYTES ((256 * XS_STRIDE + 32 * 128 + 128) * 4)

__global__ void __launch_bounds__(256, 1)
vq_main_kernel(const float* __restrict__ x,
               float* __restrict__ out_tok,
               float* __restrict__ out_idx) {
    extern __shared__ float smem[];
    float* xs  = smem;                       // [256][130]
    float* cs  = xs + 256 * XS_STRIDE;       // [32][128]
    float* c2s = cs + 32 * 128;              // [128]

    const int tid = threadIdx.x;             // 256 threads
    const int tx  = tid & 15;                // code direction   (16)
    const int ty  = tid >> 4;                // token direction  (16)
    const int blockTok = blockIdx.x * BM;

    // per-thread staging geometry for cs (code-slice) loads
    const int st_r  = tid >> 1;              // code row within chunk (0..127)
    const int st_dh = (tid & 1) * 16;        // 16-dim half within 32-dim slice

    // ---- stage full x tile (transposed): thread covers token tid/2, dim-half (tid&1)*128
    {
        const int t     = tid >> 1;
        const int dbase = (tid & 1) * 128;
        const float4* xg = reinterpret_cast<const float4*>(
            x + (size_t)(blockTok + t) * D + dbase);
        #pragma unroll
        for (int i = 0; i < 32; ++i) {
            float4 v = xg[i];
            int d = dbase + i * 4;
            xs[(d + 0) * XS_STRIDE + t] = v.x;
            xs[(d + 1) * XS_STRIDE + t] = v.y;
            xs[(d + 2) * XS_STRIDE + t] = v.z;
            xs[(d + 3) * XS_STRIDE + t] = v.w;
        }
    }

    float bestS[8];
    int   bestI[8];
    #pragma unroll
    for (int i = 0; i < 8; ++i) { bestS[i] = 3.0e38f; bestI[i] = 0; }

    // ---- prefetch slice 0 into registers (hides LDG latency behind compute)
    float4 pf[4];
    {
        const float4* cg = reinterpret_cast<const float4*>(
            g_sub + (size_t)st_r * D + st_dh);
        #pragma unroll
        for (int i = 0; i < 4; ++i) pf[i] = cg[i];
    }

    for (int ch = 0; ch < NCHUNK; ++ch) {
        if (tid < 128) c2s[tid] = g_c2[ch * BK + tid];

        float2 acc[4][8];
        #pragma unroll
        for (int p = 0; p < 4; ++p)
            #pragma unroll
            for (int j = 0; j < 8; ++j) acc[p][j] = make_float2(0.f, 0.f);

        for (int ds = 0; ds < 8; ++ds) {
            __syncthreads();   // consumers of previous cs contents are done
            // store prefetched slice into cs[32][128] (transposed)
            #pragma unroll
            for (int i = 0; i < 4; ++i) {
                int dd = st_dh + i * 4;
                cs[(dd + 0) * 128 + st_r] = pf[i].x;
                cs[(dd + 1) * 128 + st_r] = pf[i].y;
                cs[(dd + 2) * 128 + st_r] = pf[i].z;
                cs[(dd + 3) * 128 + st_r] = pf[i].w;
            }
            // issue LDGs for the NEXT slice now; latency hides behind the dd loop
            {
                int s_next = ch * 8 + ds + 1;
                if (s_next > NSLICE - 1) s_next = NSLICE - 1;   // clamp (dead data)
                const int ch_n = s_next >> 3;
                const int ds_n = s_next & 7;
                const float4* cg = reinterpret_cast<const float4*>(
                    g_sub + (size_t)(ch_n * BK + st_r) * D + ds_n * 32 + st_dh);
                #pragma unroll
                for (int i = 0; i < 4; ++i) pf[i] = cg[i];
            }
            __syncthreads();   // cs ready for everyone

            #pragma unroll 8
            for (int dd = 0; dd < 32; ++dd) {
                const int d = ds * 32 + dd;
                const float* xrow = xs + d * XS_STRIDE + ty * 8;
                float2 a0 = *reinterpret_cast<const float2*>(xrow + 0);
                float2 a1 = *reinterpret_cast<const float2*>(xrow + 2);
                float2 a2 = *reinterpret_cast<const float2*>(xrow + 4);
                float2 a3 = *reinterpret_cast<const float2*>(xrow + 6);
                const float* crow = cs + dd * 128 + tx * 8;
                float4 cA = *reinterpret_cast<const float4*>(crow);
                float4 cB = *reinterpret_cast<const float4*>(crow + 4);
                float cv[8] = {cA.x, cA.y, cA.z, cA.w, cB.x, cB.y, cB.z, cB.w};
                #pragma unroll
                for (int j = 0; j < 8; ++j) {
                    float2 cj = make_float2(cv[j], cv[j]);
                    ffma2(acc[0][j], a0, cj);
                    ffma2(acc[1][j], a1, cj);
                    ffma2(acc[2][j], a2, cj);
                    ffma2(acc[3][j], a3, cj);
                }
            }
        }
        __syncthreads();   // acc done; c2s stable; safe before next chunk restage

        // chunk epilogue: score s = c2 - 2*dot, running argmin (ascending k ⇒ '<' keeps lowest)
        #pragma unroll
        for (int j = 0; j < 8; ++j) {
            float c2v = c2s[tx * 8 + j];
            int   kk  = ch * BK + tx * 8 + j;
            #pragma unroll
            for (int p = 0; p < 4; ++p) {
                float s0 = fmaf(-2.0f, acc[p][j].x, c2v);
                float s1 = fmaf(-2.0f, acc[p][j].y, c2v);
                int t0 = p * 2, t1 = p * 2 + 1;
                if (s0 < bestS[t0]) { bestS[t0] = s0; bestI[t0] = kk; }
                if (s1 < bestS[t1]) { bestS[t1] = s1; bestI[t1] = kk; }
            }
        }
        __syncthreads();
    }

    // ---- cross-tx argmin reduce (red overlays cs: [128 tokens][16 tx] float2)
    float2* red = reinterpret_cast<float2*>(cs);
    #pragma unroll
    for (int l = 0; l < 8; ++l) {
        int t = ty * 8 + l;
        red[t * 16 + tx] = make_float2(bestS[l], __int_as_float(bestI[l]));
    }
    __syncthreads();

    int* bestk = reinterpret_cast<int*>(c2s);   // [128]
    if (tid < 128) {
        float bs = 3.0e38f; int bi = 0x7fffffff;
        #pragma unroll
        for (int e = 0; e < 16; ++e) {
            float2 v = red[tid * 16 + e];
            int vi = __float_as_int(v.y);
            if (v.x < bs || (v.x == bs && vi < bi)) { bs = v.x; bi = vi; }
        }
        bestk[tid] = bi;
        out_idx[blockTok + tid] = (float)g_gidx[bi];
    }
    __syncthreads();

    // ---- gather tokens, write output, accumulate loss (x re-read from smem)
    float lacc = 0.0f;
    #pragma unroll 4
    for (int t = 0; t < BM; ++t) {
        const float* row = g_sub + (size_t)bestk[t] * D;   // row base off critical path
        float val = __ldg(row + tid);                      // coalesced, L2-hot
        float xv  = xs[tid * XS_STRIDE + t];
        float df  = val - xv;
        lacc = fmaf(df, df, lacc);
        out_tok[(size_t)(blockTok + t) * D + tid] = val;
    }
    // block reduce lacc
    #pragma unroll
    for (int off = 16; off > 0; off >>= 1)
        lacc += __shfl_down_sync(0xffffffffu, lacc, off);
    float* lred = cs;   // cs free now
    if ((tid & 31) == 0) lred[tid >> 5] = lacc;
    __syncthreads();
    if (tid == 0) {
        float tot = 0.0f;
        #pragma unroll
        for (int w = 0; w < 8; ++w) tot += lred[w];
        atomicAdd(&g_loss, tot);
    }
}

// ---------------- Kernel C: finalize loss ----------------
__global__ void loss_kernel(float* __restrict__ out_loss) {
    out_loss[0] = g_loss * (1.0f / (float)NTOKEL);
}

// ---------------- launch ----------------
extern "C" void kernel_launch(void* const* d_in, const int* in_sizes, int n_in,
                              void* d_out, int out_size) {
    const float* x        = (const float*)d_in[0];   // [32,512,256]
    const float* codebook = (const float*)d_in[1];   // [4096,256]
    const int*   rind     = (const int*)d_in[2];     // [3686]
    float* out = (float*)d_out;
    // flattened-concat layout in reference return order:
    // tokens [4194304] | loss [1] | indices [16384]
    float* out_tok  = out;
    float* out_loss = out + NTOKEL;
    float* out_idx  = out + NTOKEL + 1;

    cudaFuncSetAttribute(vq_main_kernel,
                         cudaFuncAttributeMaxDynamicSharedMemorySize,
                         SMEM_B_BYTES);

    pack_kernel<<<KPAD, 64>>>(codebook, rind);
    vq_main_kernel<<<NTOK / BM, 256, SMEM_B_BYTES>>>(x, out_tok, out_idx);
    loss_kernel<<<1, 1>>>(out_loss);
}

// round 8
// speedup vs baseline: 1.0248x; 1.0248x over previous
#include <cuda_runtime.h>
#include <cuda_bf16.h>
#include <cstdint>

// Problem constants (shapes are fixed by the dataset)
#define D      256
#define KSUB   3686
#define KPAD   3712          // 29 * 128
#define NCHUNK 29
#define BK     128           // codes per chunk
#define BM     128           // tokens per block
#define NTOK   16384         // 32*512
#define NTOKEL 4194304       // NTOK * D
#define NSLICE (NCHUNK * 8)  // 232 ds-slices total

// ---------------- device scratch (no allocations allowed) ----------------
__device__ float g_sub[KPAD * D];    // packed (dropout-subsampled) codebook, padded
__device__ float g_c2[KPAD];         // per-code squared norms (pad rows = +huge)
__device__ int   g_gidx[KPAD];       // global codebook index per packed row
__device__ float g_loss;             // loss accumulator

// packed f32x2 FMA: d += a * b (elementwise on the pair) — Blackwell FFMA2
__device__ __forceinline__ void ffma2(float2& d, const float2& a, const float2& b) {
    unsigned long long&       dd = reinterpret_cast<unsigned long long&>(d);
    const unsigned long long& aa = reinterpret_cast<const unsigned long long&>(a);
    const unsigned long long& bb = reinterpret_cast<const unsigned long long&>(b);
    asm("fma.rn.f32x2 %0, %1, %2, %0;" : "+l"(dd) : "l"(aa), "l"(bb));
}

// ---------------- Kernel A: gather sub-codebook + c2, zero loss ----------------
__global__ void pack_kernel(const float* __restrict__ codebook,
                            const int*   __restrict__ rind) {
    int r   = blockIdx.x;          // packed row 0..KPAD-1
    int tid = threadIdx.x;         // 64 threads, one float4 each (256 floats/row)
    if (r == 0 && tid == 0) g_loss = 0.0f;

    __shared__ float sh[2];
    float4 v;
    int gi = 0;
    if (r < KSUB) {
        gi = rind[r];
        v = reinterpret_cast<const float4*>(codebook + (size_t)gi * D)[tid];
    } else {
        v = make_float4(0.f, 0.f, 0.f, 0.f);
    }
    reinterpret_cast<float4*>(g_sub + (size_t)r * D)[tid] = v;

    float s = v.x * v.x + v.y * v.y + v.z * v.z + v.w * v.w;
    #pragma unroll
    for (int off = 16; off > 0; off >>= 1)
        s += __shfl_down_sync(0xffffffffu, s, off);
    if ((tid & 31) == 0) sh[tid >> 5] = s;
    __syncthreads();
    if (tid == 0) {
        g_c2[r]   = (r < KSUB) ? (sh[0] + sh[1]) : 1.0e30f;
        g_gidx[r] = gi;
    }
}

// ---------------- Kernel B: fused GEMM-argmin + gather + loss ----------------
// smem layout (floats):
//   xs   [256][130]   : transposed x tile, 33280 floats
//   cs   [2][32][128] : DOUBLE-BUFFERED transposed code-dim slice (8192 floats)
//   c2s  [2][128]     : double-buffered per-chunk c2
//   (cs reused after mainloop as argmin scratch; c2s[0] as bestk)
#define XS_STRIDE 130
#define SMEM_B_BYTES ((256 * XS_STRIDE + 2 * 32 * 128 + 2 * 128) * 4)

__global__ void __launch_bounds__(256, 1)
vq_main_kernel(const float* __restrict__ x,
               float* __restrict__ out_tok,
               float* __restrict__ out_idx) {
    extern __shared__ float smem[];
    float* xs   = smem;                        // [256][130]
    float* csb  = xs + 256 * XS_STRIDE;        // [2][32][128]
    float* c2sb = csb + 2 * 32 * 128;          // [2][128]

    const int tid = threadIdx.x;               // 256 threads
    const int tx  = tid & 15;                  // code direction   (16)
    const int ty  = tid >> 4;                  // token direction  (16)
    const int blockTok = blockIdx.x * BM;

    // per-thread staging geometry for cs (code-slice) loads
    const int st_r  = tid >> 1;                // code row within chunk (0..127)
    const int st_dh = (tid & 1) * 16;          // 16-dim half within 32-dim slice

    // ---- stage full x tile (transposed): thread covers token tid/2, dim-half (tid&1)*128
    {
        const int t     = tid >> 1;
        const int dbase = (tid & 1) * 128;
        const float4* xg = reinterpret_cast<const float4*>(
            x + (size_t)(blockTok + t) * D + dbase);
        #pragma unroll
        for (int i = 0; i < 32; ++i) {
            float4 v = xg[i];
            int d = dbase + i * 4;
            xs[(d + 0) * XS_STRIDE + t] = v.x;
            xs[(d + 1) * XS_STRIDE + t] = v.y;
            xs[(d + 2) * XS_STRIDE + t] = v.z;
            xs[(d + 3) * XS_STRIDE + t] = v.w;
        }
    }

    float bestS[8];
    int   bestI[8];
    #pragma unroll
    for (int i = 0; i < 8; ++i) { bestS[i] = 3.0e38f; bestI[i] = 0; }

    // ---- prefetch slice 0 into registers
    float4 pf[4];
    {
        const float4* cg = reinterpret_cast<const float4*>(
            g_sub + (size_t)st_r * D + st_dh);
        #pragma unroll
        for (int i = 0; i < 4; ++i) pf[i] = cg[i];
    }

    float2 acc[4][8];
    #pragma unroll
    for (int p = 0; p < 4; ++p)
        #pragma unroll
        for (int j = 0; j < 8; ++j) acc[p][j] = make_float2(0.f, 0.f);

    // ---- flattened slice loop: ONE barrier per slice via double buffering ----
    for (int s = 0; s < NSLICE; ++s) {
        float* cs = csb + (s & 1) * (32 * 128);

        // chunk-start: load c2 into this chunk's buffer (readers of this buffer
        // last touched it 2 chunks ago, ≥8 barriers back — safe)
        if ((s & 7) == 0 && tid < 128)
            c2sb[((s >> 3) & 1) * 128 + tid] = g_c2[(s >> 3) * BK + tid];

        // store prefetched slice into cs (other buffer's readers: last iter, pre-barrier)
        #pragma unroll
        for (int i = 0; i < 4; ++i) {
            int dd = st_dh + i * 4;
            cs[(dd + 0) * 128 + st_r] = pf[i].x;
            cs[(dd + 1) * 128 + st_r] = pf[i].y;
            cs[(dd + 2) * 128 + st_r] = pf[i].z;
            cs[(dd + 3) * 128 + st_r] = pf[i].w;
        }
        // issue LDGs for the NEXT slice; latency + STS drain hide behind compute
        {
            int s_next = (s + 1 < NSLICE) ? s + 1 : NSLICE - 1;   // clamp (dead data)
            const int ch_n = s_next >> 3;
            const int ds_n = s_next & 7;
            const float4* cg = reinterpret_cast<const float4*>(
                g_sub + (size_t)(ch_n * BK + st_r) * D + ds_n * 32 + st_dh);
            #pragma unroll
            for (int i = 0; i < 4; ++i) pf[i] = cg[i];
        }
        __syncthreads();   // cs ready; prior buffer's readers all arrived

        const int ds = s & 7;
        #pragma unroll 8
        for (int dd = 0; dd < 32; ++dd) {
            const int d = ds * 32 + dd;
            const float* xrow = xs + d * XS_STRIDE + ty * 8;
            float2 a0 = *reinterpret_cast<const float2*>(xrow + 0);
            float2 a1 = *reinterpret_cast<const float2*>(xrow + 2);
            float2 a2 = *reinterpret_cast<const float2*>(xrow + 4);
            float2 a3 = *reinterpret_cast<const float2*>(xrow + 6);
            const float* crow = cs + dd * 128 + tx * 8;
            float4 cA = *reinterpret_cast<const float4*>(crow);
            float4 cB = *reinterpret_cast<const float4*>(crow + 4);
            float cv[8] = {cA.x, cA.y, cA.z, cA.w, cB.x, cB.y, cB.z, cB.w};
            #pragma unroll
            for (int j = 0; j < 8; ++j) {
                float2 cj = make_float2(cv[j], cv[j]);
                ffma2(acc[0][j], a0, cj);
                ffma2(acc[1][j], a1, cj);
                ffma2(acc[2][j], a2, cj);
                ffma2(acc[3][j], a3, cj);
            }
        }

        // chunk-end epilogue: score s = c2 - 2*dot, running argmin, reset acc
        if ((s & 7) == 7) {
            const int   ch   = s >> 3;
            const float* c2s = c2sb + (ch & 1) * 128;
            #pragma unroll
            for (int j = 0; j < 8; ++j) {
                float c2v = c2s[tx * 8 + j];
                int   kk  = ch * BK + tx * 8 + j;
                #pragma unroll
                for (int p = 0; p < 4; ++p) {
                    float s0 = fmaf(-2.0f, acc[p][j].x, c2v);
                    float s1 = fmaf(-2.0f, acc[p][j].y, c2v);
                    int t0 = p * 2, t1 = p * 2 + 1;
                    if (s0 < bestS[t0]) { bestS[t0] = s0; bestI[t0] = kk; }
                    if (s1 < bestS[t1]) { bestS[t1] = s1; bestI[t1] = kk; }
                    acc[p][j] = make_float2(0.f, 0.f);
                }
            }
        }
    }
    __syncthreads();   // all compute/epilogue done before overlaying cs as scratch

    // ---- cross-tx argmin reduce (red overlays csb: [128 tokens][16 tx] float2)
    float2* red = reinterpret_cast<float2*>(csb);
    #pragma unroll
    for (int l = 0; l < 8; ++l) {
        int t = ty * 8 + l;
        red[t * 16 + tx] = make_float2(bestS[l], __int_as_float(bestI[l]));
    }
    __syncthreads();

    int* bestk = reinterpret_cast<int*>(c2sb);   // [128]
    if (tid < 128) {
        float bs = 3.0e38f; int bi = 0x7fffffff;
        #pragma unroll
        for (int e = 0; e < 16; ++e) {
            float2 v = red[tid * 16 + e];
            int vi = __float_as_int(v.y);
            if (v.x < bs || (v.x == bs && vi < bi)) { bs = v.x; bi = vi; }
        }
        bestk[tid] = bi;
        out_idx[blockTok + tid] = (float)g_gidx[bi];
    }
    __syncthreads();

    // ---- gather tokens, write output, accumulate loss (x re-read from smem)
    float lacc = 0.0f;
    #pragma unroll 4
    for (int t = 0; t < BM; ++t) {
        const float* row = g_sub + (size_t)bestk[t] * D;   // row base off critical path
        float val = __ldg(row + tid);                      // coalesced, L2-hot
        float xv  = xs[tid * XS_STRIDE + t];
        float df  = val - xv;
        lacc = fmaf(df, df, lacc);
        out_tok[(size_t)(blockTok + t) * D + tid] = val;
    }
    // block reduce lacc
    #pragma unroll
    for (int off = 16; off > 0; off >>= 1)
        lacc += __shfl_down_sync(0xffffffffu, lacc, off);
    float* lred = csb;   // free now
    if ((tid & 31) == 0) lred[tid >> 5] = lacc;
    __syncthreads();
    if (tid == 0) {
        float tot = 0.0f;
        #pragma unroll
        for (int w = 0; w < 8; ++w) tot += lred[w];
        atomicAdd(&g_loss, tot);
    }
}

// ---------------- Kernel C: finalize loss ----------------
__global__ void loss_kernel(float* __restrict__ out_loss) {
    out_loss[0] = g_loss * (1.0f / (float)NTOKEL);
}

// ---------------- launch ----------------
extern "C" void kernel_launch(void* const* d_in, const int* in_sizes, int n_in,
                              void* d_out, int out_size) {
    const float* x        = (const float*)d_in[0];   // [32,512,256]
    const float* codebook = (const float*)d_in[1];   // [4096,256]
    const int*   rind     = (const int*)d_in[2];     // [3686]
    float* out = (float*)d_out;
    // flattened-concat layout in reference return order (CONFIRMED R6):
    // tokens [4194304] | loss [1] | indices [16384]
    float* out_tok  = out;
    float* out_loss = out + NTOKEL;
    float* out_idx  = out + NTOKEL + 1;

    cudaFuncSetAttribute(vq_main_kernel,
                         cudaFuncAttributeMaxDynamicSharedMemorySize,
                         SMEM_B_BYTES);

    pack_kernel<<<KPAD, 64>>>(codebook, rind);
    vq_main_kernel<<<NTOK / BM, 256, SMEM_B_BYTES>>>(x, out_tok, out_idx);
    loss_kernel<<<1, 1>>>(out_loss);
}